// round 1
// baseline (speedup 1.0000x reference)
#include <cuda_runtime.h>
#include <stdint.h>

#define NCOL 4096
#define TPB  256
#define EPT  (NCOL / TPB)   // 16 elements per thread
#define KSEL 64

// float -> order-preserving uint32 (larger float => larger key, unsigned compare)
__device__ __forceinline__ uint32_t f2k(float f) {
    uint32_t u = __float_as_uint(f);
    return (u & 0x80000000u) ? ~u : (u | 0x80000000u);
}
// inverse
__device__ __forceinline__ float k2f(uint32_t k) {
    uint32_t u = (k & 0x80000000u) ? (k ^ 0x80000000u) : ~k;
    return __uint_as_float(u);
}

// inclusive block scan over TPB=256 uint32 values. wsum: shared[8].
__device__ __forceinline__ uint32_t block_scan_inc(uint32_t val, uint32_t* wsum, int t) {
    __syncthreads();                 // protect wsum WAR from previous use
    int lane = t & 31, w = t >> 5;
#pragma unroll
    for (int off = 1; off < 32; off <<= 1) {
        uint32_t n = __shfl_up_sync(0xffffffffu, val, off);
        if (lane >= off) val += n;
    }
    if (lane == 31) wsum[w] = val;
    __syncthreads();
    if (w == 0) {
        uint32_t s = (lane < 8) ? wsum[lane] : 0u;
#pragma unroll
        for (int off = 1; off < 8; off <<= 1) {
            uint32_t n = __shfl_up_sync(0xffffffffu, s, off);
            if (lane >= off) s += n;
        }
        if (lane < 8) wsum[lane] = s;
    }
    __syncthreads();
    uint32_t base = (w > 0) ? wsum[w - 1] : 0u;
    return val + base;
}

__global__ __launch_bounds__(TPB) void topk_mask_kernel(const float* __restrict__ x,
                                                        float* __restrict__ out) {
    __shared__ uint32_t skey[NCOL];     // 16 KB: keys, later reused for output bits
    __shared__ uint32_t hist[256];
    __shared__ uint32_t wsum[8];
    __shared__ uint32_t s_bin, s_above;

    const int t   = threadIdx.x;
    const size_t row_off = (size_t)blockIdx.x * NCOL;
    const float4* __restrict__ xr = (const float4*)(x + row_off);
    float4* __restrict__ outr     = (float4*)(out + row_off);

    // ---- coalesced load, convert to sortable keys in SMEM ----
#pragma unroll
    for (int v = 0; v < EPT / 4; v++) {           // 4 float4s per thread
        int idx = v * TPB + t;                    // float4 index within row
        float4 f = xr[idx];
        uint4 u;
        u.x = f2k(f.x); u.y = f2k(f.y); u.z = f2k(f.z); u.w = f2k(f.w);
        ((uint4*)skey)[idx] = u;
    }
    __syncthreads();

    // ---- exact radix select: find K-th largest key (4 passes of 8 bits, MSB first) ----
    uint32_t prefix = 0, mask = 0;
    uint32_t kth = KSEL;
#pragma unroll
    for (int pass = 0; pass < 4; pass++) {
        const int shift = 24 - 8 * pass;
        hist[t] = 0;
        __syncthreads();
#pragma unroll
        for (int v = 0; v < EPT; v++) {
            uint32_t kk = skey[v * TPB + t];      // conflict-free strided read
            if ((kk & mask) == prefix)
                atomicAdd(&hist[(kk >> shift) & 0xFFu], 1u);
        }
        __syncthreads();
        // suffix sums: S(bin b) = sum_{j>=b} hist[j]; scan in reversed index r = 255 - b
        uint32_t h = hist[255 - t];
        uint32_t S = block_scan_inc(h, wsum, t);
        if (S >= kth && (S - h) < kth) {          // unique boundary thread
            s_bin   = (uint32_t)(255 - t);
            s_above = S - h;                      // count strictly above this bin
        }
        __syncthreads();
        prefix |= (s_bin << shift);
        mask   |= (0xFFu << shift);
        kth    -= s_above;
        __syncthreads();
    }
    const uint32_t T    = prefix;   // exact key of the K-th largest element
    const uint32_t need = kth;      // how many elements == T to keep (lowest indices first)

    // ---- tie ranks: index-ordered rank among elements equal to T ----
    const int base = t * EPT;       // blocked ownership for index order
    uint32_t cnt = 0;
#pragma unroll
    for (int i = 0; i < EPT; i++) cnt += (skey[base + i] == T) ? 1u : 0u;
    uint32_t inc = block_scan_inc(cnt, wsum, t);
    uint32_t r = inc - cnt;         // exclusive rank base for this thread's chunk

    // ---- produce masked values in-place in SMEM (blocked; only own chunk touched) ----
#pragma unroll
    for (int i = 0; i < EPT; i++) {
        uint32_t kk = skey[base + i];
        float outv = 0.0f;
        if (kk > T) {
            outv = k2f(kk);
        } else if (kk == T) {
            if (r < need) outv = k2f(kk);
            r++;
        }
        skey[base + i] = __float_as_uint(outv);
    }
    __syncthreads();

    // ---- coalesced store ----
#pragma unroll
    for (int v = 0; v < EPT / 4; v++) {
        int idx = v * TPB + t;
        uint4 u = ((uint4*)skey)[idx];
        float4 f;
        f.x = __uint_as_float(u.x); f.y = __uint_as_float(u.y);
        f.z = __uint_as_float(u.z); f.w = __uint_as_float(u.w);
        outr[idx] = f;
    }
}

extern "C" void kernel_launch(void* const* d_in, const int* in_sizes, int n_in,
                              void* d_out, int out_size) {
    const float* x = (const float*)d_in[0];
    float* out = (float*)d_out;
    int rows = in_sizes[0] / NCOL;
    topk_mask_kernel<<<rows, TPB>>>(x, out);
}

// round 2
// speedup vs baseline: 2.6647x; 2.6647x over previous
#include <cuda_runtime.h>
#include <stdint.h>

#define NCOL   4096
#define TPB    256
#define EPT    16          // elements per thread (NCOL / TPB)
#define KSEL   64
#define TIECAP 4096

// float -> order-preserving uint32 (larger float => larger unsigned key)
__device__ __forceinline__ uint32_t f2k(float f) {
    uint32_t u = __float_as_uint(f);
    return (u & 0x80000000u) ? ~u : (u | 0x80000000u);
}
__device__ __forceinline__ float k2f(uint32_t k) {
    uint32_t u = (k & 0x80000000u) ? (k ^ 0x80000000u) : ~k;
    return __uint_as_float(u);
}

// inclusive block scan over TPB=256 uint32 values. wsum: shared[8].
__device__ __forceinline__ uint32_t block_scan_inc(uint32_t val, uint32_t* wsum, int t) {
    __syncthreads();                 // protect wsum WAR from previous use
    int lane = t & 31, w = t >> 5;
#pragma unroll
    for (int off = 1; off < 32; off <<= 1) {
        uint32_t n = __shfl_up_sync(0xffffffffu, val, off);
        if (lane >= off) val += n;
    }
    if (lane == 31) wsum[w] = val;
    __syncthreads();
    if (w == 0) {
        uint32_t s = (lane < 8) ? wsum[lane] : 0u;
#pragma unroll
        for (int off = 1; off < 8; off <<= 1) {
            uint32_t n = __shfl_up_sync(0xffffffffu, s, off);
            if (lane >= off) s += n;
        }
        if (lane < 8) wsum[lane] = s;
    }
    __syncthreads();
    uint32_t base = (w > 0) ? wsum[w - 1] : 0u;
    return val + base;
}

__global__ __launch_bounds__(TPB, 8) void topk_mask_kernel(const float* __restrict__ x,
                                                           float* __restrict__ out) {
    __shared__ uint32_t hist[256];
    __shared__ uint32_t wsum[8];
    __shared__ uint32_t s_bin, s_above;
    __shared__ uint32_t s_eqcnt;
    __shared__ uint16_t tiebuf[TIECAP];       // worst case: every element equals T
    __shared__ uint32_t keep_bm[NCOL / 32];   // only used on the rare tie path

    const int t    = threadIdx.x;
    const int lane = t & 31;
    const size_t row_off = (size_t)blockIdx.x * NCOL;
    const float4* __restrict__ xr = (const float4*)(x + row_off);
    float4* __restrict__ outr     = (float4*)(out + row_off);

    // ---- coalesced load, keys live in registers ----
    uint32_t k[EPT];
#pragma unroll
    for (int v = 0; v < EPT / 4; v++) {
        float4 f = xr[v * TPB + t];
        k[4 * v + 0] = f2k(f.x);
        k[4 * v + 1] = f2k(f.y);
        k[4 * v + 2] = f2k(f.z);
        k[4 * v + 3] = f2k(f.w);
    }

    // ---- exact radix select over registers, warp-aggregated histogram atomics ----
    uint32_t prefix = 0, mmask = 0;
    uint32_t kth = KSEL;
#pragma unroll
    for (int pass = 0; pass < 4; pass++) {
        const int shift = 24 - 8 * pass;
        hist[t] = 0;
        __syncthreads();
#pragma unroll
        for (int e = 0; e < EPT; e++) {
            uint32_t kk = k[e];
            if ((kk & mmask) == prefix) {
                uint32_t bin = (kk >> shift) & 0xFFu;
                unsigned act = __activemask();
                unsigned grp = __match_any_sync(act, bin);
                if ((grp & ((1u << lane) - 1u)) == 0u)      // lowest lane of group
                    atomicAdd(&hist[bin], (uint32_t)__popc(grp));
            }
        }
        __syncthreads();
        // suffix sums: S(bin b) = sum_{j>=b} hist[j]; scan reversed bins
        uint32_t h = hist[255 - t];
        uint32_t S = block_scan_inc(h, wsum, t);
        if (S >= kth && (S - h) < kth) {                     // unique boundary thread
            s_bin   = (uint32_t)(255 - t);
            s_above = S - h;
        }
        __syncthreads();
        prefix |= (s_bin << shift);
        mmask  |= (0xFFu << shift);
        kth    -= s_above;
        __syncthreads();
    }
    const uint32_t T    = prefix;   // exact key of the K-th largest element
    const uint32_t need = kth;      // how many elements == T to keep (lowest cols first)

    // ---- tie handling: gather columns of elements == T ----
    if (t == 0) s_eqcnt = 0;
    __syncthreads();
#pragma unroll
    for (int e = 0; e < EPT; e++) {
        if (k[e] == T) {
            int v = e >> 2, j = e & 3;
            uint32_t col = (uint32_t)(v * TPB + t) * 4u + (uint32_t)j;
            uint32_t pos = atomicAdd(&s_eqcnt, 1u);
            tiebuf[pos] = (uint16_t)col;
        }
    }
    __syncthreads();
    const uint32_t total_eq = s_eqcnt;
    const bool all_keep = (total_eq <= need);   // common case: keep every tie
    if (!all_keep) {                            // rare: rank ties by column, keep lowest `need`
        for (int i = t; i < NCOL / 32; i += TPB) keep_bm[i] = 0;
        __syncthreads();
        for (uint32_t i = t; i < total_eq; i += TPB) {
            uint32_t ci = tiebuf[i], r = 0;
            for (uint32_t j = 0; j < total_eq; j++) r += (tiebuf[j] < ci) ? 1u : 0u;
            if (r < need) atomicOr(&keep_bm[ci >> 5], 1u << (ci & 31));
        }
        __syncthreads();
    }

    // ---- masked output straight from registers, coalesced ----
#pragma unroll
    for (int v = 0; v < EPT / 4; v++) {
        float4 o;
        float* op = (float*)&o;
#pragma unroll
        for (int j = 0; j < 4; j++) {
            uint32_t kk = k[4 * v + j];
            float val = 0.0f;
            if (kk > T) {
                val = k2f(kk);
            } else if (kk == T) {
                if (all_keep) {
                    val = k2f(kk);
                } else {
                    uint32_t col = (uint32_t)(v * TPB + t) * 4u + (uint32_t)j;
                    if ((keep_bm[col >> 5] >> (col & 31)) & 1u) val = k2f(kk);
                }
            }
            op[j] = val;
        }
        outr[v * TPB + t] = o;
    }
}

extern "C" void kernel_launch(void* const* d_in, const int* in_sizes, int n_in,
                              void* d_out, int out_size) {
    const float* x = (const float*)d_in[0];
    float* out = (float*)d_out;
    int rows = in_sizes[0] / NCOL;
    topk_mask_kernel<<<rows, TPB>>>(x, out);
}